// round 15
// baseline (speedup 1.0000x reference)
#include <cuda_runtime.h>
#include <cuda_fp16.h>
#include <cstdint>

#define NNODES 100000
#define EEDGES 1600000
#define HID    128
#define NCLS   40

// ---------------- scratch (device globals; no allocation allowed) ------------
__device__ __align__(128) __half g_hA[NNODES * HID];
__device__ __align__(128) __half g_hB[NNODES * HID];
__device__ __align__(128) __half g_wb[5 * HID * HID];    // [slot][n][k] fp16
__device__ __align__(128) __half g_wc[48 * HID];         // padded classifier W [n][k]
__device__ int   g_outdeg[NNODES];
__device__ int   g_indeg[NNODES];
__device__ int   g_cursor[NNODES];
__device__ float g_onorm[NNODES];
__device__ float g_inorm[NNODES];
__device__ int   g_rowoff[NNODES + 1];
__device__ int   g_bsums[256];
__device__ int   g_esrc[EEDGES];

// ---------------- PTX helpers -------------------------------------------------
__device__ __forceinline__ uint32_t smem_u32(const void* p) {
    uint32_t a;
    asm("{ .reg .u64 t; cvta.to.shared.u64 t, %1; cvt.u32.u64 %0, t; }" : "=r"(a) : "l"(p));
    return a;
}

#define LDSM4(r, addr)                                                          \
    asm volatile("ldmatrix.sync.aligned.m8n8.x4.shared.b16 {%0,%1,%2,%3}, [%4];" \
        : "=r"((r)[0]), "=r"((r)[1]), "=r"((r)[2]), "=r"((r)[3]) : "r"(addr))

#define MMA16816(d, a, b0, b1)                                                  \
    asm("mma.sync.aligned.m16n8k16.row.col.f32.f16.f16.f32 "                    \
        "{%0,%1,%2,%3}, {%4,%5,%6,%7}, {%8,%9}, {%0,%1,%2,%3};"                 \
        : "+f"((d)[0]), "+f"((d)[1]), "+f"((d)[2]), "+f"((d)[3])                \
        : "r"((a)[0]), "r"((a)[1]), "r"((a)[2]), "r"((a)[3]), "r"(b0), "r"(b1))

#define CP_ASYNC16(smem_addr, gptr)                                             \
    asm volatile("cp.async.ca.shared.global [%0], [%1], 16;"                    \
        :: "r"(smem_addr), "l"(gptr))
#define CP_ASYNC16Z(smem_addr, gptr, nbytes)                                    \
    asm volatile("cp.async.ca.shared.global [%0], [%1], 16, %2;"                \
        :: "r"(smem_addr), "l"(gptr), "r"(nbytes))
#define CP_COMMIT() asm volatile("cp.async.commit_group;" ::: "memory")
#define CP_WAIT0()  asm volatile("cp.async.wait_group 0;" ::: "memory")
#define CP_WAIT1()  asm volatile("cp.async.wait_group 1;" ::: "memory")

// ---------------- small prep kernels ----------------------------------------
__global__ void zero_ints_kernel(int n) {
    int i = blockIdx.x * blockDim.x + threadIdx.x;
    if (i < n) { g_outdeg[i] = 0; g_indeg[i] = 0; g_cursor[i] = 0; }
}

__global__ void degree_kernel(const int* __restrict__ src,
                              const int* __restrict__ dst, int E) {
    int e = blockIdx.x * blockDim.x + threadIdx.x;
    if (e < E) {
        atomicAdd(&g_outdeg[src[e]], 1);
        atomicAdd(&g_indeg[dst[e]], 1);
    }
}

__global__ void norm_kernel(int n) {
    int i = blockIdx.x * blockDim.x + threadIdx.x;
    if (i < n) {
        g_onorm[i] = rsqrtf((float)max(g_outdeg[i], 1));
        g_inorm[i] = rsqrtf((float)max(g_indeg[i], 1));
    }
}

__global__ void scan1_kernel(int n) {
    __shared__ int s[1024];
    int tid = threadIdx.x;
    int i = blockIdx.x * 1024 + tid;
    int v = (i < n) ? g_indeg[i] : 0;
    s[tid] = v;
    __syncthreads();
    #pragma unroll
    for (int off = 1; off < 1024; off <<= 1) {
        int t = 0;
        if (tid >= off) t = s[tid - off];
        __syncthreads();
        s[tid] += t;
        __syncthreads();
    }
    if (i < n) g_rowoff[i] = s[tid] - v;
    if (tid == 1023) g_bsums[blockIdx.x] = s[1023];
}

__global__ void scan2_kernel(int nb, int n, int E) {
    if (threadIdx.x == 0 && blockIdx.x == 0) {
        int run = 0;
        for (int b = 0; b < nb; b++) { int t = g_bsums[b]; g_bsums[b] = run; run += t; }
        g_rowoff[n] = E;
    }
}

__global__ void scan3_kernel(int n) {
    int i = blockIdx.x * 1024 + threadIdx.x;
    if (i < n) g_rowoff[i] += g_bsums[blockIdx.x];
}

__global__ void fill_kernel(const int* __restrict__ src,
                            const int* __restrict__ dst, int E) {
    int e = blockIdx.x * blockDim.x + threadIdx.x;
    if (e < E) {
        int d = dst[e];
        int pos = g_rowoff[d] + atomicAdd(&g_cursor[d], 1);
        g_esrc[pos] = src[e];
    }
}

// ---------------- converters --------------------------------------------------
__global__ void convert_x_kernel(const float* __restrict__ x,
                                 __half* __restrict__ o, int total) {
    int i = blockIdx.x * blockDim.x + threadIdx.x;
    if (i < total) o[i] = __float2half_rn(x[i]);
}

__global__ void convert_w_kernel(const float* __restrict__ W, int L,
                                 __half* __restrict__ o) {
    int i = blockIdx.x * blockDim.x + threadIdx.x;
    if (i < L * HID * HID) {
        int l = i / (HID * HID);
        int r = i - l * HID * HID;
        int n = r >> 7;
        int k = r & 127;
        o[i] = __float2half_rn(W[l * HID * HID + k * HID + n]);
    }
}

__global__ void convert_wc_kernel(const float* __restrict__ Wc,
                                  __half* __restrict__ o) {
    int i = blockIdx.x * blockDim.x + threadIdx.x;
    if (i < 48 * HID) {
        int n = i >> 7;
        int k = i & 127;
        o[i] = __float2half_rn((n < NCLS) ? Wc[k * NCLS + n] : 0.f);
    }
}

// ---------------- plain HMMA GEMM (front layers): C = A @ W + b --------------
#define SM_BIAS 0
#define SM_W    512
#define SM_ACH  (SM_W + 32768)
#define SM_TOTAL (SM_ACH + 2 * 16384)

__global__ void __launch_bounds__(256, 2)
gemm_mma_kernel(const __half* __restrict__ A,
                const __half* __restrict__ W,
                const float* __restrict__ bias,
                __half* __restrict__ C,
                int M, int relu) {
    extern __shared__ char smem[];
    uint32_t sb = smem_u32(smem);
    const int tid = threadIdx.x;
    const int lane = tid & 31;
    const int wid = tid >> 5;
    const int rowBase = blockIdx.x << 7;

    #pragma unroll
    for (int it = 0; it < 8; it++) {
        int chunk = tid + it * 256;
        int row = chunk >> 4;
        int cc = chunk & 15;
        uint32_t so = (uint32_t)(row * 256 + ((cc ^ (row & 7)) << 4));
        CP_ASYNC16(sb + SM_W + so, (const char*)(W + row * HID + cc * 8));
    }
    if (tid < 128) ((float*)smem)[tid] = bias[tid];
    CP_COMMIT();                                   // G0: W

    auto issueA = [&](int c, int buf) {
        #pragma unroll
        for (int j = 0; j < 4; j++) {
            int id = tid + j * 256;
            int row = id >> 3;
            int s = id & 7;
            int gRow = rowBase + row;
            const __half* gsrc = A + (size_t)gRow * HID + c * 64 + s * 8;
            uint32_t daddr = sb + SM_ACH + buf * 16384 + row * 128
                           + ((s ^ (row & 7)) << 4);
            int nb = (gRow < M) ? 16 : 0;
            CP_ASYNC16Z(daddr, (const char*)gsrc, nb);
        }
        CP_COMMIT();
    };

    issueA(0, 0);                                  // G1
    issueA(1, 1);                                  // G2

    const int warpRow = (wid & 3) * 32;
    const int warpCol = (wid >> 2) * 64;
    float acc[2][8][4];
    #pragma unroll
    for (int mi = 0; mi < 2; mi++)
        #pragma unroll
        for (int nt = 0; nt < 8; nt++)
            #pragma unroll
            for (int q = 0; q < 4; q++) acc[mi][nt][q] = 0.f;

    const int lr = (lane & 7) + (lane & 8);
    const int lk = (lane & 16) >> 1;

    #pragma unroll
    for (int c = 0; c < 2; c++) {
        if (c == 1) { CP_WAIT0(); } else { CP_WAIT1(); }
        __syncthreads();
        const uint32_t abase = sb + SM_ACH + c * 16384;
        #pragma unroll
        for (int ks = 0; ks < 4; ks++) {
            const int kic = ks * 16 + lk;
            const int sA = kic >> 3;
            uint32_t ah[2][4], bh[4][4];
            #pragma unroll
            for (int mi = 0; mi < 2; mi++) {
                int row = warpRow + mi * 16 + lr;
                LDSM4(ah[mi], abase + row * 128 + ((sA ^ (row & 7)) << 4));
            }
            const int kc = (c * 64 + kic) >> 3;
            #pragma unroll
            for (int nj = 0; nj < 4; nj++) {
                int row = warpCol + nj * 16 + lr;
                LDSM4(bh[nj], sb + SM_W + row * 256 + ((kc ^ (row & 7)) << 4));
            }
            #pragma unroll
            for (int mi = 0; mi < 2; mi++)
                #pragma unroll
                for (int nt = 0; nt < 8; nt++) {
                    int nj = nt >> 1, up = nt & 1;
                    MMA16816(acc[mi][nt], ah[mi], bh[nj][0 + up], bh[nj][2 + up]);
                }
        }
    }

    const int grp = lane >> 2, qid = lane & 3;
    #pragma unroll
    for (int mi = 0; mi < 2; mi++) {
        #pragma unroll
        for (int nt = 0; nt < 8; nt++) {
            int col = warpCol + nt * 8 + qid * 2;
            float b0 = ((float*)smem)[col];
            float b1 = ((float*)smem)[col + 1];
            int r0 = rowBase + warpRow + mi * 16 + grp;
            float v0 = acc[mi][nt][0] + b0, v1 = acc[mi][nt][1] + b1;
            float v2 = acc[mi][nt][2] + b0, v3 = acc[mi][nt][3] + b1;
            if (relu) {
                v0 = fmaxf(v0, 0.f); v1 = fmaxf(v1, 0.f);
                v2 = fmaxf(v2, 0.f); v3 = fmaxf(v3, 0.f);
            }
            if (r0 < M)
                *(__half2*)(C + (size_t)r0 * HID + col) = __floats2half2_rn(v0, v1);
            if (r0 + 8 < M)
                *(__half2*)(C + (size_t)(r0 + 8) * HID + col) = __floats2half2_rn(v2, v3);
        }
    }
}

// ---------------- FUSED gather + HMMA GEMM per GraphConv layer ----------------
// CTA handles 128 dst nodes: each warp gathers 16 node rows (fp32 accumulate,
// 8-edge unroll) directly into the smem A tile (256B rows, 16-slot XOR swizzle
// == W tile layout), then the block runs the K=128 HMMA. Removes the 51MB/layer
// intermediate round-trip. smem = 512 + 32KB (W) + 32KB (A) = 65.5KB, 2 CTA/SM.
#define SF_BIAS 0
#define SF_W    512
#define SF_A    (SF_W + 32768)
#define SF_TOTAL (SF_A + 32768)

__global__ void __launch_bounds__(256, 2)
gconv_fused_kernel(const __half* __restrict__ hbuf,
                   const __half* __restrict__ W,
                   const float* __restrict__ bias,
                   __half* __restrict__ C, int M) {
    extern __shared__ char smem[];
    uint32_t sb = smem_u32(smem);
    const int tid = threadIdx.x;
    const int lane = tid & 31;
    const int wid = tid >> 5;
    const int rowBase = blockIdx.x << 7;

    // W tile + bias via cp.async (overlaps the gather phase)
    #pragma unroll
    for (int it = 0; it < 8; it++) {
        int chunk = tid + it * 256;
        int row = chunk >> 4;
        int cc = chunk & 15;
        uint32_t so = (uint32_t)(row * 256 + ((cc ^ (row & 7)) << 4));
        CP_ASYNC16(sb + SF_W + so, (const char*)(W + row * HID + cc * 8));
    }
    if (tid < 128) ((float*)smem)[tid] = bias[tid];
    CP_COMMIT();

    // ---- gather phase: warp w fills rows [w*16, w*16+16) of the A tile ----
    const int slot = lane >> 1;                     // 16B slot 0..15
    const uint32_t stoff = (uint32_t)((lane & 1) << 3);
    for (int i = 0; i < 16; i++) {
        int r = wid * 16 + i;
        int gw = rowBase + r;
        float a0 = 0.f, a1 = 0.f, a2 = 0.f, a3 = 0.f;
        if (gw < M) {
            int e = g_rowoff[gw];
            int e1 = g_rowoff[gw + 1];
            for (; e + 7 < e1; e += 8) {
                int   sx[8];
                float wx[8];
                uint2 ux[8];
                #pragma unroll
                for (int j = 0; j < 8; j++) sx[j] = g_esrc[e + j];
                #pragma unroll
                for (int j = 0; j < 8; j++) wx[j] = g_onorm[sx[j]];
                #pragma unroll
                for (int j = 0; j < 8; j++)
                    ux[j] = ((const uint2*)(hbuf + (size_t)sx[j] * HID))[lane];
                #pragma unroll
                for (int j = 0; j < 8; j++) {
                    float2 p0 = __half22float2(*(__half2*)&ux[j].x);
                    float2 p1 = __half22float2(*(__half2*)&ux[j].y);
                    a0 = fmaf(p0.x, wx[j], a0); a1 = fmaf(p0.y, wx[j], a1);
                    a2 = fmaf(p1.x, wx[j], a2); a3 = fmaf(p1.y, wx[j], a3);
                }
            }
            for (; e < e1; e++) {
                int s0 = g_esrc[e];
                float w0 = g_onorm[s0];
                uint2 u0 = ((const uint2*)(hbuf + (size_t)s0 * HID))[lane];
                float2 p0 = __half22float2(*(__half2*)&u0.x);
                float2 p1 = __half22float2(*(__half2*)&u0.y);
                a0 = fmaf(p0.x, w0, a0); a1 = fmaf(p0.y, w0, a1);
                a2 = fmaf(p1.x, w0, a2); a3 = fmaf(p1.y, w0, a3);
            }
            float inn = g_inorm[gw];
            a0 *= inn; a1 *= inn; a2 *= inn; a3 *= inn;
        }
        uint2 pk;
        *(__half2*)&pk.x = __floats2half2_rn(a0, a1);
        *(__half2*)&pk.y = __floats2half2_rn(a2, a3);
        uint32_t daddr = (uint32_t)(SF_A + r * 256 + ((slot ^ (r & 7)) << 4)) + stoff;
        *(uint2*)(smem + daddr) = pk;
    }

    CP_WAIT0();
    __syncthreads();

    // ---- MMA phase: K=128 from smem A (256B rows) and W tiles ----
    const int warpRow = (wid & 3) * 32;
    const int warpCol = (wid >> 2) * 64;
    float acc[2][8][4];
    #pragma unroll
    for (int mi = 0; mi < 2; mi++)
        #pragma unroll
        for (int nt = 0; nt < 8; nt++)
            #pragma unroll
            for (int q = 0; q < 4; q++) acc[mi][nt][q] = 0.f;

    const int lr = (lane & 7) + (lane & 8);
    const int lk = (lane & 16) >> 1;

    #pragma unroll
    for (int ks = 0; ks < 8; ks++) {
        const int kic = ks * 16 + lk;               // 0..120
        const int kc = kic >> 3;                    // slot 0..15
        uint32_t ah[2][4], bh[4][4];
        #pragma unroll
        for (int mi = 0; mi < 2; mi++) {
            int row = warpRow + mi * 16 + lr;
            LDSM4(ah[mi], sb + SF_A + row * 256 + ((kc ^ (row & 7)) << 4));
        }
        #pragma unroll
        for (int nj = 0; nj < 4; nj++) {
            int row = warpCol + nj * 16 + lr;
            LDSM4(bh[nj], sb + SF_W + row * 256 + ((kc ^ (row & 7)) << 4));
        }
        #pragma unroll
        for (int mi = 0; mi < 2; mi++)
            #pragma unroll
            for (int nt = 0; nt < 8; nt++) {
                int nj = nt >> 1, up = nt & 1;
                MMA16816(acc[mi][nt], ah[mi], bh[nj][0 + up], bh[nj][2 + up]);
            }
    }

    // ---- epilogue: bias + relu -> fp16 ----
    const int grp = lane >> 2, qid = lane & 3;
    #pragma unroll
    for (int mi = 0; mi < 2; mi++) {
        #pragma unroll
        for (int nt = 0; nt < 8; nt++) {
            int col = warpCol + nt * 8 + qid * 2;
            float b0 = ((float*)smem)[col];
            float b1 = ((float*)smem)[col + 1];
            int r0 = rowBase + warpRow + mi * 16 + grp;
            float v0 = fmaxf(acc[mi][nt][0] + b0, 0.f);
            float v1 = fmaxf(acc[mi][nt][1] + b1, 0.f);
            float v2 = fmaxf(acc[mi][nt][2] + b0, 0.f);
            float v3 = fmaxf(acc[mi][nt][3] + b1, 0.f);
            if (r0 < M)
                *(__half2*)(C + (size_t)r0 * HID + col) = __floats2half2_rn(v0, v1);
            if (r0 + 8 < M)
                *(__half2*)(C + (size_t)(r0 + 8) * HID + col) = __floats2half2_rn(v2, v3);
        }
    }
}

// ---------------- classifier HMMA: out[M,40] = A[M,128] @ Wc + bc -------------
#define SMC_BC  0
#define SMC_W   256
#define SMC_ACH (SMC_W + 48 * 256)
#define SMC_TOTAL (SMC_ACH + 2 * 16384)

__global__ void __launch_bounds__(256)
cls_mma_kernel(const __half* __restrict__ A,
               const __half* __restrict__ Wc,
               const float* __restrict__ bc, float* __restrict__ out, int M) {
    extern __shared__ char smem[];
    uint32_t sb = smem_u32(smem);
    const int tid = threadIdx.x;
    const int lane = tid & 31;
    const int wid = tid >> 5;
    const int rowBase = blockIdx.x << 7;

    #pragma unroll
    for (int it = 0; it < 3; it++) {
        int chunk = tid + it * 256;
        int row = chunk >> 4;
        int cc = chunk & 15;
        uint32_t so = (uint32_t)(row * 256 + ((cc ^ (row & 7)) << 4));
        CP_ASYNC16(sb + SMC_W + so, (const char*)(Wc + row * HID + cc * 8));
    }
    if (tid < NCLS) ((float*)smem)[tid] = bc[tid];
    CP_COMMIT();

    auto issueA = [&](int c, int buf) {
        #pragma unroll
        for (int j = 0; j < 4; j++) {
            int id = tid + j * 256;
            int row = id >> 3;
            int s = id & 7;
            int gRow = rowBase + row;
            const __half* gsrc = A + (size_t)gRow * HID + c * 64 + s * 8;
            uint32_t daddr = sb + SMC_ACH + buf * 16384 + row * 128
                           + ((s ^ (row & 7)) << 4);
            int nb = (gRow < M) ? 16 : 0;
            CP_ASYNC16Z(daddr, (const char*)gsrc, nb);
        }
        CP_COMMIT();
    };
    issueA(0, 0);
    issueA(1, 1);

    const int warpRow = wid * 16;
    float acc[6][4];
    #pragma unroll
    for (int nt = 0; nt < 6; nt++)
        #pragma unroll
        for (int q = 0; q < 4; q++) acc[nt][q] = 0.f;

    const int lr = (lane & 7) + (lane & 8);
    const int lk = (lane & 16) >> 1;

    #pragma unroll
    for (int c = 0; c < 2; c++) {
        if (c == 1) { CP_WAIT0(); } else { CP_WAIT1(); }
        __syncthreads();
        const uint32_t abase = sb + SMC_ACH + c * 16384;
        #pragma unroll
        for (int ks = 0; ks < 4; ks++) {
            const int kic = ks * 16 + lk;
            const int sA = kic >> 3;
            uint32_t ah[4], bh[3][4];
            {
                int row = warpRow + lr;
                LDSM4(ah, abase + row * 128 + ((sA ^ (row & 7)) << 4));
            }
            const int kc = (c * 64 + kic) >> 3;
            #pragma unroll
            for (int nj = 0; nj < 3; nj++) {
                int row = nj * 16 + lr;
                LDSM4(bh[nj], sb + SMC_W + row * 256 + ((kc ^ (row & 7)) << 4));
            }
            #pragma unroll
            for (int nt = 0; nt < 6; nt++) {
                int nj = nt >> 1, up = nt & 1;
                MMA16816(acc[nt], ah, bh[nj][0 + up], bh[nj][2 + up]);
            }
        }
    }

    const int grp = lane >> 2, qid = lane & 3;
    #pragma unroll
    for (int nt = 0; nt < 6; nt++) {
        int col = nt * 8 + qid * 2;
        if (col < NCLS) {
            float b0 = ((float*)smem)[col];
            float b1 = ((float*)smem)[col + 1];
            int r0 = rowBase + warpRow + grp;
            if (r0 < M)
                *(float2*)(out + (size_t)r0 * NCLS + col)
                    = make_float2(acc[nt][0] + b0, acc[nt][1] + b1);
            if (r0 + 8 < M)
                *(float2*)(out + (size_t)(r0 + 8) * NCLS + col)
                    = make_float2(acc[nt][2] + b0, acc[nt][3] + b1);
        }
    }
}

// ---------------- launch ------------------------------------------------------
extern "C" void kernel_launch(void* const* d_in, const int* in_sizes, int n_in,
                              void* d_out, int out_size) {
    const float* x   = (const float*)d_in[0];
    const int*   src = (const int*)  d_in[1];
    const int*   dst = (const int*)  d_in[2];
    const float* W1  = (const float*)d_in[3];
    const float* b1  = (const float*)d_in[4];
    const float* W2  = (const float*)d_in[5];
    const float* b2  = (const float*)d_in[6];
    const float* Wg  = (const float*)d_in[7];
    const float* bg  = (const float*)d_in[8];
    const float* Wc  = (const float*)d_in[9];
    const float* bc  = (const float*)d_in[10];
    float* out = (float*)d_out;

    const int N = in_sizes[0] / HID;
    const int E = in_sizes[1];

    __half *hA, *hB, *wb, *wc;
    cudaGetSymbolAddress((void**)&hA, g_hA);
    cudaGetSymbolAddress((void**)&hB, g_hB);
    cudaGetSymbolAddress((void**)&wb, g_wb);
    cudaGetSymbolAddress((void**)&wc, g_wc);

    // once-only resource setup (handles only; identical WORK every call)
    static cudaStream_t sPrep = nullptr;
    static cudaEvent_t evFork = nullptr, evJoin = nullptr;
    if (!sPrep) {
        cudaStreamCreateWithFlags(&sPrep, cudaStreamNonBlocking);
        cudaEventCreateWithFlags(&evFork, cudaEventDisableTiming);
        cudaEventCreateWithFlags(&evJoin, cudaEventDisableTiming);
        cudaFuncSetAttribute(gemm_mma_kernel,
                             cudaFuncAttributeMaxDynamicSharedMemorySize, SM_TOTAL);
        cudaFuncSetAttribute(gconv_fused_kernel,
                             cudaFuncAttributeMaxDynamicSharedMemorySize, SF_TOTAL);
        cudaFuncSetAttribute(cls_mma_kernel,
                             cudaFuncAttributeMaxDynamicSharedMemorySize, SMC_TOTAL);
    }

    const int TB = 256;
    const int gN = (N + TB - 1) / TB;
    const int gE = (E + TB - 1) / TB;
    const int nb = (N + 1023) / 1024;
    const int gGemm = (N + 127) / 128;

    // ---- fork: prep chain (CSR build) on sPrep, concurrent with front GEMMs --
    cudaEventRecord(evFork, 0);
    cudaStreamWaitEvent(sPrep, evFork, 0);

    convert_x_kernel<<<(N * HID + TB - 1) / TB, TB>>>(x, hA, N * HID);                       // k1
    convert_w_kernel<<<(1 * HID * HID + TB - 1) / TB, TB>>>(W1, 1, wb + 0 * HID * HID);      // k2
    zero_ints_kernel<<<gN, TB, 0, sPrep>>>(N);                                               // k3 (side)
    gemm_mma_kernel<<<gGemm, TB, SM_TOTAL>>>(hA, wb + 0 * HID * HID, b1, hB, N, 0);          // k4 <- profiled

    degree_kernel<<<gE, TB, 0, sPrep>>>(src, dst, E);
    norm_kernel<<<gN, TB, 0, sPrep>>>(N);
    scan1_kernel<<<nb, 1024, 0, sPrep>>>(N);
    scan2_kernel<<<1, 32, 0, sPrep>>>(nb, N, E);
    scan3_kernel<<<nb, 1024, 0, sPrep>>>(N);
    fill_kernel<<<gE, TB, 0, sPrep>>>(src, dst, E);
    cudaEventRecord(evJoin, sPrep);

    convert_w_kernel<<<(1 * HID * HID + TB - 1) / TB, TB>>>(W2, 1, wb + 1 * HID * HID);
    convert_w_kernel<<<(3 * HID * HID + TB - 1) / TB, TB>>>(Wg, 3, wb + 2 * HID * HID);
    convert_wc_kernel<<<(48 * HID + TB - 1) / TB, TB>>>(Wc, wc);
    gemm_mma_kernel<<<gGemm, TB, SM_TOTAL>>>(hB, wb + 1 * HID * HID, b2, hA, N, 0);

    // join: CSR ready before first fused layer
    cudaStreamWaitEvent(0, evJoin, 0);

    // ---- 3 fused GraphConv layers (gather + GEMM + ReLU in one kernel) ----
    gconv_fused_kernel<<<gGemm, TB, SF_TOTAL>>>(hA, wb + 2 * HID * HID, bg + 0 * HID, hB, N);
    gconv_fused_kernel<<<gGemm, TB, SF_TOTAL>>>(hB, wb + 3 * HID * HID, bg + 1 * HID, hA, N);
    gconv_fused_kernel<<<gGemm, TB, SF_TOTAL>>>(hA, wb + 4 * HID * HID, bg + 2 * HID, hB, N);

    // ---- classifier ----
    cls_mma_kernel<<<gGemm, TB, SMC_TOTAL>>>(hB, wc, bc, out, N);
}

// round 16
// speedup vs baseline: 1.3358x; 1.3358x over previous
#include <cuda_runtime.h>
#include <cuda_fp16.h>
#include <cstdint>

#define NNODES 100000
#define EEDGES 1600000
#define HID    128
#define NCLS   40

// ---------------- scratch (device globals; no allocation allowed) ------------
__device__ __align__(128) __half g_hA[NNODES * HID];
__device__ __align__(128) __half g_hB[NNODES * HID];
__device__ __align__(128) __half g_wb[5 * HID * HID];    // [slot][n][k] fp16
__device__ __align__(128) __half g_wc[48 * HID];         // padded classifier W [n][k]
__device__ int   g_outdeg[NNODES];
__device__ int   g_indeg[NNODES];
__device__ int   g_cursor[NNODES];
__device__ float g_onorm[NNODES];
__device__ float g_inorm[NNODES];
__device__ int   g_rowoff[NNODES + 1];
__device__ int   g_bsums[256];
__device__ int   g_esrc[EEDGES];

// ---------------- PTX helpers -------------------------------------------------
__device__ __forceinline__ uint32_t smem_u32(const void* p) {
    uint32_t a;
    asm("{ .reg .u64 t; cvta.to.shared.u64 t, %1; cvt.u32.u64 %0, t; }" : "=r"(a) : "l"(p));
    return a;
}

#define LDSM4(r, addr)                                                          \
    asm volatile("ldmatrix.sync.aligned.m8n8.x4.shared.b16 {%0,%1,%2,%3}, [%4];" \
        : "=r"((r)[0]), "=r"((r)[1]), "=r"((r)[2]), "=r"((r)[3]) : "r"(addr))

#define MMA16816(d, a, b0, b1)                                                  \
    asm("mma.sync.aligned.m16n8k16.row.col.f32.f16.f16.f32 "                    \
        "{%0,%1,%2,%3}, {%4,%5,%6,%7}, {%8,%9}, {%0,%1,%2,%3};"                 \
        : "+f"((d)[0]), "+f"((d)[1]), "+f"((d)[2]), "+f"((d)[3])                \
        : "r"((a)[0]), "r"((a)[1]), "r"((a)[2]), "r"((a)[3]), "r"(b0), "r"(b1))

#define CP_ASYNC16(smem_addr, gptr)                                             \
    asm volatile("cp.async.ca.shared.global [%0], [%1], 16;"                    \
        :: "r"(smem_addr), "l"(gptr))
#define CP_ASYNC16Z(smem_addr, gptr, nbytes)                                    \
    asm volatile("cp.async.ca.shared.global [%0], [%1], 16, %2;"                \
        :: "r"(smem_addr), "l"(gptr), "r"(nbytes))
#define CP_COMMIT() asm volatile("cp.async.commit_group;" ::: "memory")
#define CP_WAIT0()  asm volatile("cp.async.wait_group 0;" ::: "memory")
#define CP_WAIT1()  asm volatile("cp.async.wait_group 1;" ::: "memory")

// ---------------- small prep kernels ----------------------------------------
__global__ void zero_ints_kernel(int n) {
    int i = blockIdx.x * blockDim.x + threadIdx.x;
    if (i < n) { g_outdeg[i] = 0; g_indeg[i] = 0; g_cursor[i] = 0; }
}

__global__ void degree_kernel(const int* __restrict__ src,
                              const int* __restrict__ dst, int E) {
    int e = blockIdx.x * blockDim.x + threadIdx.x;
    if (e < E) {
        atomicAdd(&g_outdeg[src[e]], 1);
        atomicAdd(&g_indeg[dst[e]], 1);
    }
}

__global__ void norm_kernel(int n) {
    int i = blockIdx.x * blockDim.x + threadIdx.x;
    if (i < n) {
        g_onorm[i] = rsqrtf((float)max(g_outdeg[i], 1));
        g_inorm[i] = rsqrtf((float)max(g_indeg[i], 1));
    }
}

__global__ void scan1_kernel(int n) {
    __shared__ int s[1024];
    int tid = threadIdx.x;
    int i = blockIdx.x * 1024 + tid;
    int v = (i < n) ? g_indeg[i] : 0;
    s[tid] = v;
    __syncthreads();
    #pragma unroll
    for (int off = 1; off < 1024; off <<= 1) {
        int t = 0;
        if (tid >= off) t = s[tid - off];
        __syncthreads();
        s[tid] += t;
        __syncthreads();
    }
    if (i < n) g_rowoff[i] = s[tid] - v;
    if (tid == 1023) g_bsums[blockIdx.x] = s[1023];
}

__global__ void scan2_kernel(int nb, int n, int E) {
    if (threadIdx.x == 0 && blockIdx.x == 0) {
        int run = 0;
        for (int b = 0; b < nb; b++) { int t = g_bsums[b]; g_bsums[b] = run; run += t; }
        g_rowoff[n] = E;
    }
}

__global__ void scan3_kernel(int n) {
    int i = blockIdx.x * 1024 + threadIdx.x;
    if (i < n) g_rowoff[i] += g_bsums[blockIdx.x];
}

__global__ void fill_kernel(const int* __restrict__ src,
                            const int* __restrict__ dst, int E) {
    int e = blockIdx.x * blockDim.x + threadIdx.x;
    if (e < E) {
        int d = dst[e];
        int pos = g_rowoff[d] + atomicAdd(&g_cursor[d], 1);
        g_esrc[pos] = src[e];
    }
}

// ---------------- converters --------------------------------------------------
__global__ void convert_x_kernel(const float* __restrict__ x,
                                 __half* __restrict__ o, int total) {
    int i = blockIdx.x * blockDim.x + threadIdx.x;
    if (i < total) o[i] = __float2half_rn(x[i]);
}

__global__ void convert_w_kernel(const float* __restrict__ W, int L,
                                 __half* __restrict__ o) {
    int i = blockIdx.x * blockDim.x + threadIdx.x;
    if (i < L * HID * HID) {
        int l = i / (HID * HID);
        int r = i - l * HID * HID;
        int n = r >> 7;
        int k = r & 127;
        o[i] = __float2half_rn(W[l * HID * HID + k * HID + n]);
    }
}

__global__ void convert_wc_kernel(const float* __restrict__ Wc,
                                  __half* __restrict__ o) {
    int i = blockIdx.x * blockDim.x + threadIdx.x;
    if (i < 48 * HID) {
        int n = i >> 7;
        int k = i & 127;
        o[i] = __float2half_rn((n < NCLS) ? Wc[k * NCLS + n] : 0.f);
    }
}

// ---------------- gather: warp per dst node, 8-edge front-batched loads -------
// Warp-per-node with huge grid (early-exit backfill) preserves aggregate warp
// parallelism; 8-wide front-batched LDGs double per-warp MLP.
__global__ void __launch_bounds__(256)
gather_kernel(const __half* __restrict__ hbuf,
              __half* __restrict__ obuf, int n) {
    int gw = (blockIdx.x * blockDim.x + threadIdx.x) >> 5;
    int lane = threadIdx.x & 31;
    if (gw >= n) return;
    int e0 = g_rowoff[gw];
    int e1 = g_rowoff[gw + 1];
    float a0 = 0.f, a1 = 0.f, a2 = 0.f, a3 = 0.f;

    int e = e0;
    for (; e + 7 < e1; e += 8) {
        int   sx[8];
        float wx[8];
        uint2 ux[8];
        #pragma unroll
        for (int j = 0; j < 8; j++) sx[j] = g_esrc[e + j];
        #pragma unroll
        for (int j = 0; j < 8; j++) wx[j] = g_onorm[sx[j]];
        #pragma unroll
        for (int j = 0; j < 8; j++)
            ux[j] = ((const uint2*)(hbuf + (size_t)sx[j] * HID))[lane];
        #pragma unroll
        for (int j = 0; j < 8; j++) {
            float2 p0 = __half22float2(*(__half2*)&ux[j].x);
            float2 p1 = __half22float2(*(__half2*)&ux[j].y);
            a0 = fmaf(p0.x, wx[j], a0); a1 = fmaf(p0.y, wx[j], a1);
            a2 = fmaf(p1.x, wx[j], a2); a3 = fmaf(p1.y, wx[j], a3);
        }
    }
    for (; e < e1; e++) {
        int s0 = g_esrc[e];
        float w0 = g_onorm[s0];
        uint2 u0 = ((const uint2*)(hbuf + (size_t)s0 * HID))[lane];
        float2 p0 = __half22float2(*(__half2*)&u0.x);
        float2 p1 = __half22float2(*(__half2*)&u0.y);
        a0 = fmaf(p0.x, w0, a0); a1 = fmaf(p0.y, w0, a1);
        a2 = fmaf(p1.x, w0, a2); a3 = fmaf(p1.y, w0, a3);
    }

    float inn = g_inorm[gw];
    uint2 w;
    *(__half2*)&w.x = __floats2half2_rn(a0 * inn, a1 * inn);
    *(__half2*)&w.y = __floats2half2_rn(a2 * inn, a3 * inn);
    ((uint2*)(obuf + (size_t)gw * HID))[lane] = w;
}

// ---------------- HMMA GEMM: C[M,128] = A[M,128] @ W + b (pure fp16) ---------
#define SM_BIAS 0
#define SM_W    512
#define SM_ACH  (SM_W + 32768)
#define SM_TOTAL (SM_ACH + 2 * 16384)

__global__ void __launch_bounds__(256, 2)
gemm_mma_kernel(const __half* __restrict__ A,
                const __half* __restrict__ W,
                const float* __restrict__ bias,
                __half* __restrict__ C,
                int M, int relu) {
    extern __shared__ char smem[];
    uint32_t sb = smem_u32(smem);
    const int tid = threadIdx.x;
    const int lane = tid & 31;
    const int wid = tid >> 5;
    const int rowBase = blockIdx.x << 7;

    #pragma unroll
    for (int it = 0; it < 8; it++) {
        int chunk = tid + it * 256;
        int row = chunk >> 4;
        int cc = chunk & 15;
        uint32_t so = (uint32_t)(row * 256 + ((cc ^ (row & 7)) << 4));
        CP_ASYNC16(sb + SM_W + so, (const char*)(W + row * HID + cc * 8));
    }
    if (tid < 128) ((float*)smem)[tid] = bias[tid];
    CP_COMMIT();                                   // G0: W

    auto issueA = [&](int c, int buf) {
        #pragma unroll
        for (int j = 0; j < 4; j++) {
            int id = tid + j * 256;
            int row = id >> 3;
            int s = id & 7;
            int gRow = rowBase + row;
            const __half* gsrc = A + (size_t)gRow * HID + c * 64 + s * 8;
            uint32_t daddr = sb + SM_ACH + buf * 16384 + row * 128
                           + ((s ^ (row & 7)) << 4);
            int nb = (gRow < M) ? 16 : 0;
            CP_ASYNC16Z(daddr, (const char*)gsrc, nb);
        }
        CP_COMMIT();
    };

    issueA(0, 0);                                  // G1
    issueA(1, 1);                                  // G2

    const int warpRow = (wid & 3) * 32;
    const int warpCol = (wid >> 2) * 64;
    float acc[2][8][4];
    #pragma unroll
    for (int mi = 0; mi < 2; mi++)
        #pragma unroll
        for (int nt = 0; nt < 8; nt++)
            #pragma unroll
            for (int q = 0; q < 4; q++) acc[mi][nt][q] = 0.f;

    const int lr = (lane & 7) + (lane & 8);
    const int lk = (lane & 16) >> 1;

    #pragma unroll
    for (int c = 0; c < 2; c++) {
        if (c == 1) { CP_WAIT0(); } else { CP_WAIT1(); }
        __syncthreads();
        const uint32_t abase = sb + SM_ACH + c * 16384;
        #pragma unroll
        for (int ks = 0; ks < 4; ks++) {
            const int kic = ks * 16 + lk;
            const int sA = kic >> 3;
            uint32_t ah[2][4], bh[4][4];
            #pragma unroll
            for (int mi = 0; mi < 2; mi++) {
                int row = warpRow + mi * 16 + lr;
                LDSM4(ah[mi], abase + row * 128 + ((sA ^ (row & 7)) << 4));
            }
            const int kc = (c * 64 + kic) >> 3;
            #pragma unroll
            for (int nj = 0; nj < 4; nj++) {
                int row = warpCol + nj * 16 + lr;
                LDSM4(bh[nj], sb + SM_W + row * 256 + ((kc ^ (row & 7)) << 4));
            }
            #pragma unroll
            for (int mi = 0; mi < 2; mi++)
                #pragma unroll
                for (int nt = 0; nt < 8; nt++) {
                    int nj = nt >> 1, up = nt & 1;
                    MMA16816(acc[mi][nt], ah[mi], bh[nj][0 + up], bh[nj][2 + up]);
                }
        }
    }

    const int grp = lane >> 2, qid = lane & 3;
    #pragma unroll
    for (int mi = 0; mi < 2; mi++) {
        #pragma unroll
        for (int nt = 0; nt < 8; nt++) {
            int col = warpCol + nt * 8 + qid * 2;
            float b0 = ((float*)smem)[col];
            float b1 = ((float*)smem)[col + 1];
            int r0 = rowBase + warpRow + mi * 16 + grp;
            float v0 = acc[mi][nt][0] + b0, v1 = acc[mi][nt][1] + b1;
            float v2 = acc[mi][nt][2] + b0, v3 = acc[mi][nt][3] + b1;
            if (relu) {
                v0 = fmaxf(v0, 0.f); v1 = fmaxf(v1, 0.f);
                v2 = fmaxf(v2, 0.f); v3 = fmaxf(v3, 0.f);
            }
            if (r0 < M)
                *(__half2*)(C + (size_t)r0 * HID + col) = __floats2half2_rn(v0, v1);
            if (r0 + 8 < M)
                *(__half2*)(C + (size_t)(r0 + 8) * HID + col) = __floats2half2_rn(v2, v3);
        }
    }
}

// ---------------- classifier HMMA: out[M,40] = A[M,128] @ Wc + bc -------------
#define SMC_BC  0
#define SMC_W   256
#define SMC_ACH (SMC_W + 48 * 256)
#define SMC_TOTAL (SMC_ACH + 2 * 16384)

__global__ void __launch_bounds__(256)
cls_mma_kernel(const __half* __restrict__ A,
               const __half* __restrict__ Wc,
               const float* __restrict__ bc, float* __restrict__ out, int M) {
    extern __shared__ char smem[];
    uint32_t sb = smem_u32(smem);
    const int tid = threadIdx.x;
    const int lane = tid & 31;
    const int wid = tid >> 5;
    const int rowBase = blockIdx.x << 7;

    #pragma unroll
    for (int it = 0; it < 3; it++) {
        int chunk = tid + it * 256;
        int row = chunk >> 4;
        int cc = chunk & 15;
        uint32_t so = (uint32_t)(row * 256 + ((cc ^ (row & 7)) << 4));
        CP_ASYNC16(sb + SMC_W + so, (const char*)(Wc + row * HID + cc * 8));
    }
    if (tid < NCLS) ((float*)smem)[tid] = bc[tid];
    CP_COMMIT();

    auto issueA = [&](int c, int buf) {
        #pragma unroll
        for (int j = 0; j < 4; j++) {
            int id = tid + j * 256;
            int row = id >> 3;
            int s = id & 7;
            int gRow = rowBase + row;
            const __half* gsrc = A + (size_t)gRow * HID + c * 64 + s * 8;
            uint32_t daddr = sb + SMC_ACH + buf * 16384 + row * 128
                           + ((s ^ (row & 7)) << 4);
            int nb = (gRow < M) ? 16 : 0;
            CP_ASYNC16Z(daddr, (const char*)gsrc, nb);
        }
        CP_COMMIT();
    };
    issueA(0, 0);
    issueA(1, 1);

    const int warpRow = wid * 16;
    float acc[6][4];
    #pragma unroll
    for (int nt = 0; nt < 6; nt++)
        #pragma unroll
        for (int q = 0; q < 4; q++) acc[nt][q] = 0.f;

    const int lr = (lane & 7) + (lane & 8);
    const int lk = (lane & 16) >> 1;

    #pragma unroll
    for (int c = 0; c < 2; c++) {
        if (c == 1) { CP_WAIT0(); } else { CP_WAIT1(); }
        __syncthreads();
        const uint32_t abase = sb + SMC_ACH + c * 16384;
        #pragma unroll
        for (int ks = 0; ks < 4; ks++) {
            const int kic = ks * 16 + lk;
            const int sA = kic >> 3;
            uint32_t ah[4], bh[3][4];
            {
                int row = warpRow + lr;
                LDSM4(ah, abase + row * 128 + ((sA ^ (row & 7)) << 4));
            }
            const int kc = (c * 64 + kic) >> 3;
            #pragma unroll
            for (int nj = 0; nj < 3; nj++) {
                int row = nj * 16 + lr;
                LDSM4(bh[nj], sb + SMC_W + row * 256 + ((kc ^ (row & 7)) << 4));
            }
            #pragma unroll
            for (int nt = 0; nt < 6; nt++) {
                int nj = nt >> 1, up = nt & 1;
                MMA16816(acc[nt], ah, bh[nj][0 + up], bh[nj][2 + up]);
            }
        }
    }

    const int grp = lane >> 2, qid = lane & 3;
    #pragma unroll
    for (int nt = 0; nt < 6; nt++) {
        int col = nt * 8 + qid * 2;
        if (col < NCLS) {
            float b0 = ((float*)smem)[col];
            float b1 = ((float*)smem)[col + 1];
            int r0 = rowBase + warpRow + grp;
            if (r0 < M)
                *(float2*)(out + (size_t)r0 * NCLS + col)
                    = make_float2(acc[nt][0] + b0, acc[nt][1] + b1);
            if (r0 + 8 < M)
                *(float2*)(out + (size_t)(r0 + 8) * NCLS + col)
                    = make_float2(acc[nt][2] + b0, acc[nt][3] + b1);
        }
    }
}

// ---------------- launch ------------------------------------------------------
extern "C" void kernel_launch(void* const* d_in, const int* in_sizes, int n_in,
                              void* d_out, int out_size) {
    const float* x   = (const float*)d_in[0];
    const int*   src = (const int*)  d_in[1];
    const int*   dst = (const int*)  d_in[2];
    const float* W1  = (const float*)d_in[3];
    const float* b1  = (const float*)d_in[4];
    const float* W2  = (const float*)d_in[5];
    const float* b2  = (const float*)d_in[6];
    const float* Wg  = (const float*)d_in[7];
    const float* bg  = (const float*)d_in[8];
    const float* Wc  = (const float*)d_in[9];
    const float* bc  = (const float*)d_in[10];
    float* out = (float*)d_out;

    const int N = in_sizes[0] / HID;
    const int E = in_sizes[1];

    __half *hA, *hB, *wb, *wc;
    cudaGetSymbolAddress((void**)&hA, g_hA);
    cudaGetSymbolAddress((void**)&hB, g_hB);
    cudaGetSymbolAddress((void**)&wb, g_wb);
    cudaGetSymbolAddress((void**)&wc, g_wc);

    // once-only resource setup (handles only; identical WORK every call)
    static cudaStream_t sPrep = nullptr;
    static cudaEvent_t evFork = nullptr, evJoin = nullptr;
    if (!sPrep) {
        cudaStreamCreateWithFlags(&sPrep, cudaStreamNonBlocking);
        cudaEventCreateWithFlags(&evFork, cudaEventDisableTiming);
        cudaEventCreateWithFlags(&evJoin, cudaEventDisableTiming);
        cudaFuncSetAttribute(gemm_mma_kernel,
                             cudaFuncAttributeMaxDynamicSharedMemorySize, SM_TOTAL);
        cudaFuncSetAttribute(cls_mma_kernel,
                             cudaFuncAttributeMaxDynamicSharedMemorySize, SMC_TOTAL);
    }

    const int TB = 256;
    const int gN = (N + TB - 1) / TB;
    const int gE = (E + TB - 1) / TB;
    const int nb = (N + 1023) / 1024;
    const int gGemm = (N + 127) / 128;
    const int gGather = (N + 7) / 8;

    // ---- fork: prep chain (CSR build) on sPrep, concurrent with front GEMMs --
    cudaEventRecord(evFork, 0);
    cudaStreamWaitEvent(sPrep, evFork, 0);

    convert_x_kernel<<<(N * HID + TB - 1) / TB, TB>>>(x, hA, N * HID);                       // k1
    convert_w_kernel<<<(1 * HID * HID + TB - 1) / TB, TB>>>(W1, 1, wb + 0 * HID * HID);      // k2
    zero_ints_kernel<<<gN, TB, 0, sPrep>>>(N);                                               // k3 (side)
    gemm_mma_kernel<<<gGemm, TB, SM_TOTAL>>>(hA, wb + 0 * HID * HID, b1, hB, N, 0);          // k4 <- profiled

    degree_kernel<<<gE, TB, 0, sPrep>>>(src, dst, E);
    norm_kernel<<<gN, TB, 0, sPrep>>>(N);
    scan1_kernel<<<nb, 1024, 0, sPrep>>>(N);
    scan2_kernel<<<1, 32, 0, sPrep>>>(nb, N, E);
    scan3_kernel<<<nb, 1024, 0, sPrep>>>(N);
    fill_kernel<<<gE, TB, 0, sPrep>>>(src, dst, E);
    cudaEventRecord(evJoin, sPrep);

    convert_w_kernel<<<(1 * HID * HID + TB - 1) / TB, TB>>>(W2, 1, wb + 1 * HID * HID);
    convert_w_kernel<<<(3 * HID * HID + TB - 1) / TB, TB>>>(Wg, 3, wb + 2 * HID * HID);
    convert_wc_kernel<<<(48 * HID + TB - 1) / TB, TB>>>(Wc, wc);
    gemm_mma_kernel<<<gGemm, TB, SM_TOTAL>>>(hB, wb + 1 * HID * HID, b2, hA, N, 0);

    // join: CSR ready before first gather
    cudaStreamWaitEvent(0, evJoin, 0);

    gather_kernel<<<gGather, TB>>>(hA, hB, N);
    gemm_mma_kernel<<<gGemm, TB, SM_TOTAL>>>(hB, wb + 2 * HID * HID, bg + 0 * HID, hA, N, 1);

    gather_kernel<<<gGather, TB>>>(hA, hB, N);
    gemm_mma_kernel<<<gGemm, TB, SM_TOTAL>>>(hB, wb + 3 * HID * HID, bg + 1 * HID, hA, N, 1);

    gather_kernel<<<gGather, TB>>>(hA, hB, N);
    gemm_mma_kernel<<<gGemm, TB, SM_TOTAL>>>(hB, wb + 4 * HID * HID, bg + 2 * HID, hA, N, 1);

    cls_mma_kernel<<<gGemm, TB, SMC_TOTAL>>>(hA, wc, bc, out, N);
}

// round 17
// speedup vs baseline: 1.4107x; 1.0561x over previous
#include <cuda_runtime.h>
#include <cuda_fp16.h>
#include <cstdint>

#define NNODES 100000
#define EEDGES 1600000
#define HID    128
#define NCLS   40

// ---------------- scratch (device globals; no allocation allowed) ------------
__device__ __align__(128) __half g_hA[NNODES * HID];
__device__ __align__(128) __half g_hB[NNODES * HID];
__device__ __align__(128) __half g_wb[5 * HID * HID];    // [slot][n][k] fp16
__device__ __align__(128) __half g_wc[48 * HID];         // padded classifier W [n][k]
__device__ int   g_outdeg[NNODES];
__device__ int   g_indeg[NNODES];
__device__ int   g_cursor[NNODES];
__device__ float g_onorm[NNODES];
__device__ float g_inorm[NNODES];
__device__ int   g_rowoff[NNODES + 1];
__device__ int   g_bsums[256];
__device__ int   g_esrc[EEDGES];

// ---------------- PTX helpers -------------------------------------------------
__device__ __forceinline__ uint32_t smem_u32(const void* p) {
    uint32_t a;
    asm("{ .reg .u64 t; cvta.to.shared.u64 t, %1; cvt.u32.u64 %0, t; }" : "=r"(a) : "l"(p));
    return a;
}

#define LDSM4(r, addr)                                                          \
    asm volatile("ldmatrix.sync.aligned.m8n8.x4.shared.b16 {%0,%1,%2,%3}, [%4];" \
        : "=r"((r)[0]), "=r"((r)[1]), "=r"((r)[2]), "=r"((r)[3]) : "r"(addr))

#define MMA16816(d, a, b0, b1)                                                  \
    asm("mma.sync.aligned.m16n8k16.row.col.f32.f16.f16.f32 "                    \
        "{%0,%1,%2,%3}, {%4,%5,%6,%7}, {%8,%9}, {%0,%1,%2,%3};"                 \
        : "+f"((d)[0]), "+f"((d)[1]), "+f"((d)[2]), "+f"((d)[3])                \
        : "r"((a)[0]), "r"((a)[1]), "r"((a)[2]), "r"((a)[3]), "r"(b0), "r"(b1))

#define CP_ASYNC16(smem_addr, gptr)                                             \
    asm volatile("cp.async.ca.shared.global [%0], [%1], 16;"                    \
        :: "r"(smem_addr), "l"(gptr))
#define CP_ASYNC16Z(smem_addr, gptr, nbytes)                                    \
    asm volatile("cp.async.ca.shared.global [%0], [%1], 16, %2;"                \
        :: "r"(smem_addr), "l"(gptr), "r"(nbytes))
#define CP_COMMIT() asm volatile("cp.async.commit_group;" ::: "memory")
#define CP_WAIT0()  asm volatile("cp.async.wait_group 0;" ::: "memory")
#define CP_WAIT1()  asm volatile("cp.async.wait_group 1;" ::: "memory")

// ---------------- small prep kernels ----------------------------------------
__global__ void zero_ints_kernel(int n) {
    int i = blockIdx.x * blockDim.x + threadIdx.x;
    if (i < n) { g_outdeg[i] = 0; g_indeg[i] = 0; g_cursor[i] = 0; }
}

__global__ void degree_kernel(const int* __restrict__ src,
                              const int* __restrict__ dst, int E) {
    int e = blockIdx.x * blockDim.x + threadIdx.x;
    if (e < E) {
        atomicAdd(&g_outdeg[src[e]], 1);
        atomicAdd(&g_indeg[dst[e]], 1);
    }
}

__global__ void norm_kernel(int n) {
    int i = blockIdx.x * blockDim.x + threadIdx.x;
    if (i < n) {
        g_onorm[i] = rsqrtf((float)max(g_outdeg[i], 1));
        g_inorm[i] = rsqrtf((float)max(g_indeg[i], 1));
    }
}

__global__ void scan1_kernel(int n) {
    __shared__ int s[1024];
    int tid = threadIdx.x;
    int i = blockIdx.x * 1024 + tid;
    int v = (i < n) ? g_indeg[i] : 0;
    s[tid] = v;
    __syncthreads();
    #pragma unroll
    for (int off = 1; off < 1024; off <<= 1) {
        int t = 0;
        if (tid >= off) t = s[tid - off];
        __syncthreads();
        s[tid] += t;
        __syncthreads();
    }
    if (i < n) g_rowoff[i] = s[tid] - v;
    if (tid == 1023) g_bsums[blockIdx.x] = s[1023];
}

__global__ void scan2_kernel(int nb, int n, int E) {
    if (threadIdx.x == 0 && blockIdx.x == 0) {
        int run = 0;
        for (int b = 0; b < nb; b++) { int t = g_bsums[b]; g_bsums[b] = run; run += t; }
        g_rowoff[n] = E;
    }
}

__global__ void scan3_kernel(int n) {
    int i = blockIdx.x * 1024 + threadIdx.x;
    if (i < n) g_rowoff[i] += g_bsums[blockIdx.x];
}

__global__ void fill_kernel(const int* __restrict__ src,
                            const int* __restrict__ dst, int E) {
    int e = blockIdx.x * blockDim.x + threadIdx.x;
    if (e < E) {
        int d = dst[e];
        int pos = g_rowoff[d] + atomicAdd(&g_cursor[d], 1);
        g_esrc[pos] = src[e];
    }
}

// ---------------- converters --------------------------------------------------
__global__ void convert_x_kernel(const float* __restrict__ x,
                                 __half* __restrict__ o, int total) {
    int i = blockIdx.x * blockDim.x + threadIdx.x;
    if (i < total) o[i] = __float2half_rn(x[i]);
}

// W1 and W2 [k][n] fp32 -> slots 0,1 of wb as [n][k] fp16, one launch
__global__ void convert_w12_kernel(const float* __restrict__ W1,
                                   const float* __restrict__ W2,
                                   __half* __restrict__ o) {
    int i = blockIdx.x * blockDim.x + threadIdx.x;
    if (i < 2 * HID * HID) {
        int l = i >> 14;
        int r = i & (HID * HID - 1);
        int n = r >> 7;
        int k = r & 127;
        const float* W = l ? W2 : W1;
        o[i] = __float2half_rn(W[k * HID + n]);
    }
}

__global__ void convert_w_kernel(const float* __restrict__ W, int L,
                                 __half* __restrict__ o) {
    int i = blockIdx.x * blockDim.x + threadIdx.x;
    if (i < L * HID * HID) {
        int l = i / (HID * HID);
        int r = i - l * HID * HID;
        int n = r >> 7;
        int k = r & 127;
        o[i] = __float2half_rn(W[l * HID * HID + k * HID + n]);
    }
}

__global__ void convert_wc_kernel(const float* __restrict__ Wc,
                                  __half* __restrict__ o) {
    int i = blockIdx.x * blockDim.x + threadIdx.x;
    if (i < 48 * HID) {
        int n = i >> 7;
        int k = i & 127;
        o[i] = __float2half_rn((n < NCLS) ? Wc[k * NCLS + n] : 0.f);
    }
}

// ---------------- gather: warp per dst node (R12 proven form) -----------------
__global__ void __launch_bounds__(256)
gather_kernel(const __half* __restrict__ hbuf,
              __half* __restrict__ obuf, int n) {
    int gw = (blockIdx.x * blockDim.x + threadIdx.x) >> 5;
    int lane = threadIdx.x & 31;
    if (gw >= n) return;
    int e0 = g_rowoff[gw];
    int e1 = g_rowoff[gw + 1];
    float a0 = 0.f, a1 = 0.f, a2 = 0.f, a3 = 0.f;

    int e = e0;
    for (; e + 3 < e1; e += 4) {
        int s0 = g_esrc[e],     s1 = g_esrc[e + 1];
        int s2 = g_esrc[e + 2], s3 = g_esrc[e + 3];
        float w0 = g_onorm[s0], w1 = g_onorm[s1];
        float w2 = g_onorm[s2], w3 = g_onorm[s3];
        uint2 u0 = ((const uint2*)(hbuf + (size_t)s0 * HID))[lane];
        uint2 u1 = ((const uint2*)(hbuf + (size_t)s1 * HID))[lane];
        uint2 u2 = ((const uint2*)(hbuf + (size_t)s2 * HID))[lane];
        uint2 u3 = ((const uint2*)(hbuf + (size_t)s3 * HID))[lane];
        float2 f00 = __half22float2(*(__half2*)&u0.x), f01 = __half22float2(*(__half2*)&u0.y);
        float2 f10 = __half22float2(*(__half2*)&u1.x), f11 = __half22float2(*(__half2*)&u1.y);
        float2 f20 = __half22float2(*(__half2*)&u2.x), f21 = __half22float2(*(__half2*)&u2.y);
        float2 f30 = __half22float2(*(__half2*)&u3.x), f31 = __half22float2(*(__half2*)&u3.y);
        a0 = fmaf(f00.x, w0, a0); a1 = fmaf(f00.y, w0, a1);
        a2 = fmaf(f01.x, w0, a2); a3 = fmaf(f01.y, w0, a3);
        a0 = fmaf(f10.x, w1, a0); a1 = fmaf(f10.y, w1, a1);
        a2 = fmaf(f11.x, w1, a2); a3 = fmaf(f11.y, w1, a3);
        a0 = fmaf(f20.x, w2, a0); a1 = fmaf(f20.y, w2, a1);
        a2 = fmaf(f21.x, w2, a2); a3 = fmaf(f21.y, w2, a3);
        a0 = fmaf(f30.x, w3, a0); a1 = fmaf(f30.y, w3, a1);
        a2 = fmaf(f31.x, w3, a2); a3 = fmaf(f31.y, w3, a3);
    }
    for (; e < e1; e++) {
        int s0 = g_esrc[e];
        float w0 = g_onorm[s0];
        uint2 u0 = ((const uint2*)(hbuf + (size_t)s0 * HID))[lane];
        float2 f00 = __half22float2(*(__half2*)&u0.x), f01 = __half22float2(*(__half2*)&u0.y);
        a0 = fmaf(f00.x, w0, a0); a1 = fmaf(f00.y, w0, a1);
        a2 = fmaf(f01.x, w0, a2); a3 = fmaf(f01.y, w0, a3);
    }

    float inn = g_inorm[gw];
    uint2 w;
    *(__half2*)&w.x = __floats2half2_rn(a0 * inn, a1 * inn);
    *(__half2*)&w.y = __floats2half2_rn(a2 * inn, a3 * inn);
    ((uint2*)(obuf + (size_t)gw * HID))[lane] = w;
}

// ---------------- plain HMMA GEMM (layers 1,2 of GraphConv): C = A@W+b, relu --
#define SM_BIAS 0
#define SM_W    512
#define SM_ACH  (SM_W + 32768)
#define SM_TOTAL (SM_ACH + 2 * 16384)

__global__ void __launch_bounds__(256, 2)
gemm_mma_kernel(const __half* __restrict__ A,
                const __half* __restrict__ W,
                const float* __restrict__ bias,
                __half* __restrict__ C,
                int M, int relu) {
    extern __shared__ char smem[];
    uint32_t sb = smem_u32(smem);
    const int tid = threadIdx.x;
    const int lane = tid & 31;
    const int wid = tid >> 5;
    const int rowBase = blockIdx.x << 7;

    #pragma unroll
    for (int it = 0; it < 8; it++) {
        int chunk = tid + it * 256;
        int row = chunk >> 4;
        int cc = chunk & 15;
        uint32_t so = (uint32_t)(row * 256 + ((cc ^ (row & 7)) << 4));
        CP_ASYNC16(sb + SM_W + so, (const char*)(W + row * HID + cc * 8));
    }
    if (tid < 128) ((float*)smem)[tid] = bias[tid];
    CP_COMMIT();

    auto issueA = [&](int c, int buf) {
        #pragma unroll
        for (int j = 0; j < 4; j++) {
            int id = tid + j * 256;
            int row = id >> 3;
            int s = id & 7;
            int gRow = rowBase + row;
            const __half* gsrc = A + (size_t)gRow * HID + c * 64 + s * 8;
            uint32_t daddr = sb + SM_ACH + buf * 16384 + row * 128
                           + ((s ^ (row & 7)) << 4);
            int nb = (gRow < M) ? 16 : 0;
            CP_ASYNC16Z(daddr, (const char*)gsrc, nb);
        }
        CP_COMMIT();
    };

    issueA(0, 0);
    issueA(1, 1);

    const int warpRow = (wid & 3) * 32;
    const int warpCol = (wid >> 2) * 64;
    float acc[2][8][4];
    #pragma unroll
    for (int mi = 0; mi < 2; mi++)
        #pragma unroll
        for (int nt = 0; nt < 8; nt++)
            #pragma unroll
            for (int q = 0; q < 4; q++) acc[mi][nt][q] = 0.f;

    const int lr = (lane & 7) + (lane & 8);
    const int lk = (lane & 16) >> 1;

    #pragma unroll
    for (int c = 0; c < 2; c++) {
        if (c == 1) { CP_WAIT0(); } else { CP_WAIT1(); }
        __syncthreads();
        const uint32_t abase = sb + SM_ACH + c * 16384;
        #pragma unroll
        for (int ks = 0; ks < 4; ks++) {
            const int kic = ks * 16 + lk;
            const int sA = kic >> 3;
            uint32_t ah[2][4], bh[4][4];
            #pragma unroll
            for (int mi = 0; mi < 2; mi++) {
                int row = warpRow + mi * 16 + lr;
                LDSM4(ah[mi], abase + row * 128 + ((sA ^ (row & 7)) << 4));
            }
            const int kc = (c * 64 + kic) >> 3;
            #pragma unroll
            for (int nj = 0; nj < 4; nj++) {
                int row = warpCol + nj * 16 + lr;
                LDSM4(bh[nj], sb + SM_W + row * 256 + ((kc ^ (row & 7)) << 4));
            }
            #pragma unroll
            for (int mi = 0; mi < 2; mi++)
                #pragma unroll
                for (int nt = 0; nt < 8; nt++) {
                    int nj = nt >> 1, up = nt & 1;
                    MMA16816(acc[mi][nt], ah[mi], bh[nj][0 + up], bh[nj][2 + up]);
                }
        }
    }

    const int grp = lane >> 2, qid = lane & 3;
    #pragma unroll
    for (int mi = 0; mi < 2; mi++) {
        #pragma unroll
        for (int nt = 0; nt < 8; nt++) {
            int col = warpCol + nt * 8 + qid * 2;
            float b0 = ((float*)smem)[col];
            float b1 = ((float*)smem)[col + 1];
            int r0 = rowBase + warpRow + mi * 16 + grp;
            float v0 = acc[mi][nt][0] + b0, v1 = acc[mi][nt][1] + b1;
            float v2 = acc[mi][nt][2] + b0, v3 = acc[mi][nt][3] + b1;
            if (relu) {
                v0 = fmaxf(v0, 0.f); v1 = fmaxf(v1, 0.f);
                v2 = fmaxf(v2, 0.f); v3 = fmaxf(v3, 0.f);
            }
            if (r0 < M)
                *(__half2*)(C + (size_t)r0 * HID + col) = __floats2half2_rn(v0, v1);
            if (r0 + 8 < M)
                *(__half2*)(C + (size_t)(r0 + 8) * HID + col) = __floats2half2_rn(v2, v3);
        }
    }
}

// ---------------- FUSED front MLP: C = (A@W1+b1)@W2+b2 (no relu) -------------
// W1+W2 resident; after phase-1 the A-chunk smem is reused for the biased
// intermediate tile (256B rows, 16-slot swizzle), then phase-2 MMA.
#define S2_B1   0                   // 128 floats
#define S2_B2   512                 // 128 floats
#define S2_W1   1024
#define S2_W2   (S2_W1 + 32768)
#define S2_ACH  (S2_W2 + 32768)     // 2x16KB chunks; reused as intermediate
#define S2_TOTAL (S2_ACH + 2 * 16384)

__global__ void __launch_bounds__(256, 2)
gemm12_fused_kernel(const __half* __restrict__ A,
                    const __half* __restrict__ W1h, const __half* __restrict__ W2h,
                    const float* __restrict__ b1, const float* __restrict__ b2,
                    __half* __restrict__ C, int M) {
    extern __shared__ char smem[];
    uint32_t sb = smem_u32(smem);
    const int tid = threadIdx.x;
    const int lane = tid & 31;
    const int wid = tid >> 5;
    const int rowBase = blockIdx.x << 7;

    #pragma unroll
    for (int it = 0; it < 8; it++) {
        int chunk = tid + it * 256;
        int row = chunk >> 4;
        int cc = chunk & 15;
        uint32_t so = (uint32_t)(row * 256 + ((cc ^ (row & 7)) << 4));
        CP_ASYNC16(sb + S2_W1 + so, (const char*)(W1h + row * HID + cc * 8));
        CP_ASYNC16(sb + S2_W2 + so, (const char*)(W2h + row * HID + cc * 8));
    }
    if (tid < 128) {
        ((float*)smem)[tid] = b1[tid];
        ((float*)(smem + S2_B2))[tid] = b2[tid];
    }
    CP_COMMIT();

    auto issueA = [&](int c, int buf) {
        #pragma unroll
        for (int j = 0; j < 4; j++) {
            int id = tid + j * 256;
            int row = id >> 3;
            int s = id & 7;
            int gRow = rowBase + row;
            const __half* gsrc = A + (size_t)gRow * HID + c * 64 + s * 8;
            uint32_t daddr = sb + S2_ACH + buf * 16384 + row * 128
                           + ((s ^ (row & 7)) << 4);
            int nb = (gRow < M) ? 16 : 0;
            CP_ASYNC16Z(daddr, (const char*)gsrc, nb);
        }
        CP_COMMIT();
    };
    issueA(0, 0);
    issueA(1, 1);

    const int warpRow = (wid & 3) * 32;
    const int warpCol = (wid >> 2) * 64;
    float acc[2][8][4];
    #pragma unroll
    for (int mi = 0; mi < 2; mi++)
        #pragma unroll
        for (int nt = 0; nt < 8; nt++)
            #pragma unroll
            for (int q = 0; q < 4; q++) acc[mi][nt][q] = 0.f;

    const int lr = (lane & 7) + (lane & 8);
    const int lk = (lane & 16) >> 1;
    const int grp = lane >> 2, qid = lane & 3;

    // ---- phase 1: A @ W1 ----
    #pragma unroll
    for (int c = 0; c < 2; c++) {
        if (c == 1) { CP_WAIT0(); } else { CP_WAIT1(); }
        __syncthreads();
        const uint32_t abase = sb + S2_ACH + c * 16384;
        #pragma unroll
        for (int ks = 0; ks < 4; ks++) {
            const int kic = ks * 16 + lk;
            const int sA = kic >> 3;
            uint32_t ah[2][4], bh[4][4];
            #pragma unroll
            for (int mi = 0; mi < 2; mi++) {
                int row = warpRow + mi * 16 + lr;
                LDSM4(ah[mi], abase + row * 128 + ((sA ^ (row & 7)) << 4));
            }
            const int kc = (c * 64 + kic) >> 3;
            #pragma unroll
            for (int nj = 0; nj < 4; nj++) {
                int row = warpCol + nj * 16 + lr;
                LDSM4(bh[nj], sb + S2_W1 + row * 256 + ((kc ^ (row & 7)) << 4));
            }
            #pragma unroll
            for (int mi = 0; mi < 2; mi++)
                #pragma unroll
                for (int nt = 0; nt < 8; nt++) {
                    int nj = nt >> 1, up = nt & 1;
                    MMA16816(acc[mi][nt], ah[mi], bh[nj][0 + up], bh[nj][2 + up]);
                }
        }
    }

    // ---- intermediate: acc + b1 -> fp16 tile in chunk smem (256B rows) ----
    __syncthreads();
    #pragma unroll
    for (int mi = 0; mi < 2; mi++) {
        #pragma unroll
        for (int nt = 0; nt < 8; nt++) {
            int col = warpCol + nt * 8 + qid * 2;
            float b0 = ((float*)smem)[col];
            float b1v = ((float*)smem)[col + 1];
            int slot = (warpCol >> 3) + nt;
            int r0 = warpRow + mi * 16 + grp;
            int r1 = r0 + 8;
            *(__half2*)(smem + S2_ACH + r0 * 256 + ((slot ^ (r0 & 7)) << 4) + qid * 4)
                = __floats2half2_rn(acc[mi][nt][0] + b0, acc[mi][nt][1] + b1v);
            *(__half2*)(smem + S2_ACH + r1 * 256 + ((slot ^ (r1 & 7)) << 4) + qid * 4)
                = __floats2half2_rn(acc[mi][nt][2] + b0, acc[mi][nt][3] + b1v);
            #pragma unroll
            for (int q = 0; q < 4; q++) acc[mi][nt][q] = 0.f;
        }
    }
    __syncthreads();

    // ---- phase 2: intermediate @ W2 ----
    #pragma unroll
    for (int ks = 0; ks < 8; ks++) {
        const int kic = ks * 16 + lk;
        const int kc = kic >> 3;
        uint32_t ah[2][4], bh[4][4];
        #pragma unroll
        for (int mi = 0; mi < 2; mi++) {
            int row = warpRow + mi * 16 + lr;
            LDSM4(ah[mi], sb + S2_ACH + row * 256 + ((kc ^ (row & 7)) << 4));
        }
        #pragma unroll
        for (int nj = 0; nj < 4; nj++) {
            int row = warpCol + nj * 16 + lr;
            LDSM4(bh[nj], sb + S2_W2 + row * 256 + ((kc ^ (row & 7)) << 4));
        }
        #pragma unroll
        for (int mi = 0; mi < 2; mi++)
            #pragma unroll
            for (int nt = 0; nt < 8; nt++) {
                int nj = nt >> 1, up = nt & 1;
                MMA16816(acc[mi][nt], ah[mi], bh[nj][0 + up], bh[nj][2 + up]);
            }
    }

    // ---- epilogue: + b2 -> C ----
    #pragma unroll
    for (int mi = 0; mi < 2; mi++) {
        #pragma unroll
        for (int nt = 0; nt < 8; nt++) {
            int col = warpCol + nt * 8 + qid * 2;
            float b0 = ((float*)(smem + S2_B2))[col];
            float b1v = ((float*)(smem + S2_B2))[col + 1];
            int r0 = rowBase + warpRow + mi * 16 + grp;
            if (r0 < M)
                *(__half2*)(C + (size_t)r0 * HID + col)
                    = __floats2half2_rn(acc[mi][nt][0] + b0, acc[mi][nt][1] + b1v);
            if (r0 + 8 < M)
                *(__half2*)(C + (size_t)(r0 + 8) * HID + col)
                    = __floats2half2_rn(acc[mi][nt][2] + b0, acc[mi][nt][3] + b1v);
        }
    }
}

// ---------------- FUSED L3 GraphConv GEMM + classifier ------------------------
// out = relu(A@W3+b3) @ Wc + bc ; the relu'd tile never touches gmem.
#define S3_B3   0                   // 128 floats
#define S3_BC   512                 // 48 floats
#define S3_W3   1024
#define S3_WC   (S3_W3 + 32768)     // 48 rows x 256B = 12KB
#define S3_ACH  (S3_WC + 12288)     // 2x16KB chunks; reused as intermediate
#define S3_TOTAL (S3_ACH + 2 * 16384)

__global__ void __launch_bounds__(256, 2)
gconv3_cls_kernel(const __half* __restrict__ A,
                  const __half* __restrict__ W3h, const __half* __restrict__ Wch,
                  const float* __restrict__ b3, const float* __restrict__ bc,
                  float* __restrict__ out, int M) {
    extern __shared__ char smem[];
    uint32_t sb = smem_u32(smem);
    const int tid = threadIdx.x;
    const int lane = tid & 31;
    const int wid = tid >> 5;
    const int rowBase = blockIdx.x << 7;

    #pragma unroll
    for (int it = 0; it < 8; it++) {
        int chunk = tid + it * 256;
        int row = chunk >> 4;
        int cc = chunk & 15;
        uint32_t so = (uint32_t)(row * 256 + ((cc ^ (row & 7)) << 4));
        CP_ASYNC16(sb + S3_W3 + so, (const char*)(W3h + row * HID + cc * 8));
    }
    #pragma unroll
    for (int it = 0; it < 3; it++) {
        int chunk = tid + it * 256;
        int row = chunk >> 4;
        int cc = chunk & 15;
        uint32_t so = (uint32_t)(row * 256 + ((cc ^ (row & 7)) << 4));
        CP_ASYNC16(sb + S3_WC + so, (const char*)(Wch + row * HID + cc * 8));
    }
    if (tid < 128) ((float*)smem)[tid] = b3[tid];
    if (tid >= 128 && tid < 128 + NCLS) ((float*)(smem + S3_BC))[tid - 128] = bc[tid - 128];
    CP_COMMIT();

    auto issueA = [&](int c, int buf) {
        #pragma unroll
        for (int j = 0; j < 4; j++) {
            int id = tid + j * 256;
            int row = id >> 3;
            int s = id & 7;
            int gRow = rowBase + row;
            const __half* gsrc = A + (size_t)gRow * HID + c * 64 + s * 8;
            uint32_t daddr = sb + S3_ACH + buf * 16384 + row * 128
                           + ((s ^ (row & 7)) << 4);
            int nb = (gRow < M) ? 16 : 0;
            CP_ASYNC16Z(daddr, (const char*)gsrc, nb);
        }
        CP_COMMIT();
    };
    issueA(0, 0);
    issueA(1, 1);

    const int warpRow = (wid & 3) * 32;
    const int warpCol = (wid >> 2) * 64;
    float acc[2][8][4];
    #pragma unroll
    for (int mi = 0; mi < 2; mi++)
        #pragma unroll
        for (int nt = 0; nt < 8; nt++)
            #pragma unroll
            for (int q = 0; q < 4; q++) acc[mi][nt][q] = 0.f;

    const int lr = (lane & 7) + (lane & 8);
    const int lk = (lane & 16) >> 1;
    const int grp = lane >> 2, qid = lane & 3;

    // ---- phase 1: A @ W3 ----
    #pragma unroll
    for (int c = 0; c < 2; c++) {
        if (c == 1) { CP_WAIT0(); } else { CP_WAIT1(); }
        __syncthreads();
        const uint32_t abase = sb + S3_ACH + c * 16384;
        #pragma unroll
        for (int ks = 0; ks < 4; ks++) {
            const int kic = ks * 16 + lk;
            const int sA = kic >> 3;
            uint32_t ah[2][4], bh[4][4];
            #pragma unroll
            for (int mi = 0; mi < 2; mi++) {
                int row = warpRow + mi * 16 + lr;
                LDSM4(ah[mi], abase + row * 128 + ((sA ^ (row & 7)) << 4));
            }
            const int kc = (c * 64 + kic) >> 3;
            #pragma unroll
            for (int nj = 0; nj < 4; nj++) {
                int row = warpCol + nj * 16 + lr;
                LDSM4(bh[nj], sb + S3_W3 + row * 256 + ((kc ^ (row & 7)) << 4));
            }
            #pragma unroll
            for (int mi = 0; mi < 2; mi++)
                #pragma unroll
                for (int nt = 0; nt < 8; nt++) {
                    int nj = nt >> 1, up = nt & 1;
                    MMA16816(acc[mi][nt], ah[mi], bh[nj][0 + up], bh[nj][2 + up]);
                }
        }
    }

    // ---- intermediate: relu(acc + b3) -> fp16 tile in chunk smem ----
    __syncthreads();
    #pragma unroll
    for (int mi = 0; mi < 2; mi++) {
        #pragma unroll
        for (int nt = 0; nt < 8; nt++) {
            int col = warpCol + nt * 8 + qid * 2;
            float b0 = ((float*)smem)[col];
            float b1v = ((float*)smem)[col + 1];
            int slot = (warpCol >> 3) + nt;
            int r0 = warpRow + mi * 16 + grp;
            int r1 = r0 + 8;
            float v0 = fmaxf(acc[mi][nt][0] + b0, 0.f);
            float v1 = fmaxf(acc[mi][nt][1] + b1v, 0.f);
            float v2 = fmaxf(acc[mi][nt][2] + b0, 0.f);
            float v3 = fmaxf(acc[mi][nt][3] + b1v, 0.f);
            *(__half2*)(smem + S3_ACH + r0 * 256 + ((slot ^ (r0 & 7)) << 4) + qid * 4)
                = __floats2half2_rn(v0, v1);
            *(__half2*)(smem + S3_ACH + r1 * 256 + ((slot ^ (r1 & 7)) << 4) + qid * 4)
                = __floats2half2_rn(v2, v3);
        }
    }
    __syncthreads();

    // ---- phase 2: classifier MMA (warp = 16 rows x 48 cols) ----
    const int cwRow = wid * 16;
    float cacc[6][4];
    #pragma unroll
    for (int nt = 0; nt < 6; nt++)
        #pragma unroll
        for (int q = 0; q < 4; q++) cacc[nt][q] = 0.f;

    #pragma unroll
    for (int ks = 0; ks < 8; ks++) {
        const int kic = ks * 16 + lk;
        const int kc = kic >> 3;
        uint32_t ah[4], bh[3][4];
        {
            int row = cwRow + lr;
            LDSM4(ah, sb + S3_ACH + row * 256 + ((kc ^ (row & 7)) << 4));
        }
        #pragma unroll
        for (int nj = 0; nj < 3; nj++) {
            int row = nj * 16 + lr;
            LDSM4(bh[nj], sb + S3_WC + row * 256 + ((kc ^ (row & 7)) << 4));
        }
        #pragma unroll
        for (int nt = 0; nt < 6; nt++) {
            int nj = nt >> 1, up = nt & 1;
            MMA16816(cacc[nt], ah, bh[nj][0 + up], bh[nj][2 + up]);
        }
    }

    // ---- epilogue: + bc -> out fp32 ----
    #pragma unroll
    for (int nt = 0; nt < 6; nt++) {
        int col = nt * 8 + qid * 2;
        if (col < NCLS) {
            float b0 = ((float*)(smem + S3_BC))[col];
            float b1v = ((float*)(smem + S3_BC))[col + 1];
            int r0 = rowBase + cwRow + grp;
            if (r0 < M)
                *(float2*)(out + (size_t)r0 * NCLS + col)
                    = make_float2(cacc[nt][0] + b0, cacc[nt][1] + b1v);
            if (r0 + 8 < M)
                *(float2*)(out + (size_t)(r0 + 8) * NCLS + col)
                    = make_float2(cacc[nt][2] + b0, cacc[nt][3] + b1v);
        }
    }
}

// ---------------- launch ------------------------------------------------------
extern "C" void kernel_launch(void* const* d_in, const int* in_sizes, int n_in,
                              void* d_out, int out_size) {
    const float* x   = (const float*)d_in[0];
    const int*   src = (const int*)  d_in[1];
    const int*   dst = (const int*)  d_in[2];
    const float* W1  = (const float*)d_in[3];
    const float* b1  = (const float*)d_in[4];
    const float* W2  = (const float*)d_in[5];
    const float* b2  = (const float*)d_in[6];
    const float* Wg  = (const float*)d_in[7];
    const float* bg  = (const float*)d_in[8];
    const float* Wc  = (const float*)d_in[9];
    const float* bc  = (const float*)d_in[10];
    float* out = (float*)d_out;

    const int N = in_sizes[0] / HID;
    const int E = in_sizes[1];

    __half *hA, *hB, *wb, *wc;
    cudaGetSymbolAddress((void**)&hA, g_hA);
    cudaGetSymbolAddress((void**)&hB, g_hB);
    cudaGetSymbolAddress((void**)&wb, g_wb);
    cudaGetSymbolAddress((void**)&wc, g_wc);

    // once-only resource setup (handles only; identical WORK every call)
    static cudaStream_t sPrep = nullptr;
    static cudaEvent_t evFork = nullptr, evJoin = nullptr;
    if (!sPrep) {
        cudaStreamCreateWithFlags(&sPrep, cudaStreamNonBlocking);
        cudaEventCreateWithFlags(&evFork, cudaEventDisableTiming);
        cudaEventCreateWithFlags(&evJoin, cudaEventDisableTiming);
        cudaFuncSetAttribute(gemm_mma_kernel,
                             cudaFuncAttributeMaxDynamicSharedMemorySize, SM_TOTAL);
        cudaFuncSetAttribute(gemm12_fused_kernel,
                             cudaFuncAttributeMaxDynamicSharedMemorySize, S2_TOTAL);
        cudaFuncSetAttribute(gconv3_cls_kernel,
                             cudaFuncAttributeMaxDynamicSharedMemorySize, S3_TOTAL);
    }

    const int TB = 256;
    const int gN = (N + TB - 1) / TB;
    const int gE = (E + TB - 1) / TB;
    const int nb = (N + 1023) / 1024;
    const int gGemm = (N + 127) / 128;
    const int gGather = (N + 7) / 8;

    // ---- fork: prep chain (CSR build) on sPrep, concurrent with front GEMM ---
    cudaEventRecord(evFork, 0);
    cudaStreamWaitEvent(sPrep, evFork, 0);

    convert_x_kernel<<<(N * HID + TB - 1) / TB, TB>>>(x, hA, N * HID);                       // k1
    convert_w12_kernel<<<(2 * HID * HID + TB - 1) / TB, TB>>>(W1, W2, wb);                   // k2
    zero_ints_kernel<<<gN, TB, 0, sPrep>>>(N);                                               // k3 (side)
    gemm12_fused_kernel<<<gGemm, TB, S2_TOTAL>>>(hA, wb, wb + HID * HID,
                                                 b1, b2, hB, N);                             // k4 <- profiled

    degree_kernel<<<gE, TB, 0, sPrep>>>(src, dst, E);
    norm_kernel<<<gN, TB, 0, sPrep>>>(N);
    scan1_kernel<<<nb, 1024, 0, sPrep>>>(N);
    scan2_kernel<<<1, 32, 0, sPrep>>>(nb, N, E);
    scan3_kernel<<<nb, 1024, 0, sPrep>>>(N);
    fill_kernel<<<gE, TB, 0, sPrep>>>(src, dst, E);
    cudaEventRecord(evJoin, sPrep);

    convert_w_kernel<<<(3 * HID * HID + TB - 1) / TB, TB>>>(Wg, 3, wb + 2 * HID * HID);
    convert_wc_kernel<<<(48 * HID + TB - 1) / TB, TB>>>(Wc, wc);

    // join: CSR ready before first gather
    cudaStreamWaitEvent(0, evJoin, 0);

    gather_kernel<<<gGather, TB>>>(hB, hA, N);
    gemm_mma_kernel<<<gGemm, TB, SM_TOTAL>>>(hA, wb + 2 * HID * HID, bg + 0 * HID, hB, N, 1);

    gather_kernel<<<gGather, TB>>>(hB, hA, N);
    gemm_mma_kernel<<<gGemm, TB, SM_TOTAL>>>(hA, wb + 3 * HID * HID, bg + 1 * HID, hB, N, 1);

    gather_kernel<<<gGather, TB>>>(hB, hA, N);
    gconv3_cls_kernel<<<gGemm, TB, S3_TOTAL>>>(hA, wb + 4 * HID * HID, wc,
                                               bg + 2 * HID, bc, out, N);
}